// round 1
// baseline (speedup 1.0000x reference)
#include <cuda_runtime.h>

#define NN 50000
#define EE 800000
#define HH 128
#define DD 3
#define TE 32
#define TN 32

// ---------------- device scratch (no allocations allowed) ----------------
__device__ float g_agg[NN * HH];    // 25.6 MB message aggregation
__device__ float g_coord[NN * DD];  // coord aggregation
__device__ float g_cnt[NN];         // edge counts per source node

__device__ __forceinline__ float silu_f(float v) { return v / (1.0f + __expf(-v)); }
__device__ __forceinline__ float sigmoid_f(float v) { return 1.0f / (1.0f + __expf(-v)); }

// ---------------- zero scratch each launch (graph replays) ----------------
__global__ void zero_kernel() {
    const int total = NN * HH + NN * DD + NN;
    for (int i = blockIdx.x * blockDim.x + threadIdx.x; i < total;
         i += gridDim.x * blockDim.x) {
        if (i < NN * HH) g_agg[i] = 0.0f;
        else if (i < NN * HH + NN * DD) g_coord[i - NN * HH] = 0.0f;
        else g_cnt[i - NN * HH - NN * DD] = 0.0f;
    }
}

// ---------------- fused edge kernel ----------------
// Block: 128 threads (thread t owns output feature t), TE=32 edges per block.
// Phases: gather -> layer1(258->128)+SiLU -> layer2(128->128)+SiLU ->
//         attention gate -> agg scatter -> coord MLP -> coord scatter.
__global__ __launch_bounds__(128) void edge_kernel(
    const float* __restrict__ h, const float* __restrict__ x,
    const int* __restrict__ ei, const float* __restrict__ eattr,
    const float* __restrict__ EW1, const float* __restrict__ eb1,
    const float* __restrict__ EW2, const float* __restrict__ eb2,
    const float* __restrict__ CW1, const float* __restrict__ cb1,
    const float* __restrict__ CW2, const float* __restrict__ AW,
    const float* __restrict__ ab)
{
    // Aliased flat buffer:
    //   phase 1:   s_in  = sbuf[e*260 + k]   (32 x 260 = 8320 floats)
    //   phase 2+:  s_h   = sbuf[e*132 + k]   (32 x 132 = 4224)
    //              s_m   = sbuf[4224 + e*132 + k]
    __shared__ float sbuf[8448];
    __shared__ int   s_row[TE];
    __shared__ float s_cd[TE][3];
    __shared__ float s_att[TE];
    __shared__ float s_red[4][TE];

    float* s_in = sbuf;
    float* s_h  = sbuf;
    float* s_m  = sbuf + 4224;

    const int tid = threadIdx.x;
    const int e0  = blockIdx.x * TE;

    // ---- gather: h[row], h[col] coalesced; geometry by lane-per-edge ----
    #pragma unroll 4
    for (int e = 0; e < TE; ++e) {
        int idx = e0 + e; if (idx >= EE) idx = EE - 1;
        const int r = ei[idx];
        const int c = ei[EE + idx];
        s_in[e * 260 + tid]       = h[r * HH + tid];
        s_in[e * 260 + 128 + tid] = h[c * HH + tid];
    }
    if (tid < TE) {
        int idx = e0 + tid; if (idx >= EE) idx = EE - 1;
        const int r = ei[idx];
        const int c = ei[EE + idx];
        s_row[tid] = r;
        float rad = 0.0f;
        #pragma unroll
        for (int d = 0; d < 3; ++d) {
            const float df = x[r * 3 + d] - x[c * 3 + d];
            s_cd[tid][d] = df;
            rad += df * df;
        }
        s_in[tid * 260 + 256] = rad;
        s_in[tid * 260 + 257] = eattr[idx];
    }
    __syncthreads();

    float acc[TE];

    // ---- layer 1: (E,258) @ (258,128) ----
    #pragma unroll
    for (int e = 0; e < TE; ++e) acc[e] = 0.0f;
    for (int k4 = 0; k4 < 64; ++k4) {
        const int k = k4 * 4;
        const float w0 = EW1[(k + 0) * HH + tid];
        const float w1 = EW1[(k + 1) * HH + tid];
        const float w2 = EW1[(k + 2) * HH + tid];
        const float w3 = EW1[(k + 3) * HH + tid];
        #pragma unroll
        for (int e = 0; e < TE; ++e) {
            const float4 v = *(const float4*)&s_in[e * 260 + k];
            acc[e] += v.x * w0;
            acc[e] += v.y * w1;
            acc[e] += v.z * w2;
            acc[e] += v.w * w3;
        }
    }
    {   // tail: radial, edge_attr
        const float w0 = EW1[256 * HH + tid];
        const float w1 = EW1[257 * HH + tid];
        #pragma unroll
        for (int e = 0; e < TE; ++e)
            acc[e] += s_in[e * 260 + 256] * w0 + s_in[e * 260 + 257] * w1;
    }
    const float bb1 = eb1[tid];
    __syncthreads();  // all reads of s_in done before aliased overwrite
    #pragma unroll
    for (int e = 0; e < TE; ++e) s_h[e * 132 + tid] = silu_f(acc[e] + bb1);
    __syncthreads();

    // ---- layer 2: (E,128) @ (128,128) ----
    #pragma unroll
    for (int e = 0; e < TE; ++e) acc[e] = 0.0f;
    for (int k4 = 0; k4 < 32; ++k4) {
        const int k = k4 * 4;
        const float w0 = EW2[(k + 0) * HH + tid];
        const float w1 = EW2[(k + 1) * HH + tid];
        const float w2 = EW2[(k + 2) * HH + tid];
        const float w3 = EW2[(k + 3) * HH + tid];
        #pragma unroll
        for (int e = 0; e < TE; ++e) {
            const float4 v = *(const float4*)&s_h[e * 132 + k];
            acc[e] += v.x * w0;
            acc[e] += v.y * w1;
            acc[e] += v.z * w2;
            acc[e] += v.w * w3;
        }
    }
    const float bb2 = eb2[tid];
    #pragma unroll
    for (int e = 0; e < TE; ++e) s_m[e * 132 + tid] = silu_f(acc[e] + bb2);
    __syncthreads();

    // ---- attention gate: sigmoid(m @ a_w + a_b), 4-warp split reduction ----
    {
        const int e = tid & 31, q = tid >> 5;
        float s = 0.0f;
        #pragma unroll
        for (int kk = 0; kk < 32; ++kk) {
            const int k = q * 32 + kk;
            s += s_m[e * 132 + k] * AW[k];
        }
        s_red[q][e] = s;
    }
    __syncthreads();
    if (tid < TE) {
        const float s = s_red[0][tid] + s_red[1][tid] + s_red[2][tid] + s_red[3][tid] + ab[0];
        s_att[tid] = sigmoid_f(s);
    }
    __syncthreads();
    #pragma unroll
    for (int e = 0; e < TE; ++e) s_m[e * 132 + tid] *= s_att[e];
    __syncthreads();

    // ---- scatter gated messages into agg ----
    #pragma unroll
    for (int e = 0; e < TE; ++e) {
        if (e0 + e < EE)
            atomicAdd(&g_agg[s_row[e] * HH + tid], s_m[e * 132 + tid]);
    }

    // ---- coord MLP layer 1: silu(m @ c_w1 + c_b1) ----
    #pragma unroll
    for (int e = 0; e < TE; ++e) acc[e] = 0.0f;
    for (int k4 = 0; k4 < 32; ++k4) {
        const int k = k4 * 4;
        const float w0 = CW1[(k + 0) * HH + tid];
        const float w1 = CW1[(k + 1) * HH + tid];
        const float w2 = CW1[(k + 2) * HH + tid];
        const float w3 = CW1[(k + 3) * HH + tid];
        #pragma unroll
        for (int e = 0; e < TE; ++e) {
            const float4 v = *(const float4*)&s_m[e * 132 + k];
            acc[e] += v.x * w0;
            acc[e] += v.y * w1;
            acc[e] += v.z * w2;
            acc[e] += v.w * w3;
        }
    }
    const float bbc = cb1[tid];
    #pragma unroll
    for (int e = 0; e < TE; ++e) s_h[e * 132 + tid] = silu_f(acc[e] + bbc);
    __syncthreads();

    // ---- coord_update = p @ c_w2 ; scatter coord diffs + counts ----
    {
        const int e = tid & 31, q = tid >> 5;
        float s = 0.0f;
        #pragma unroll
        for (int kk = 0; kk < 32; ++kk) {
            const int k = q * 32 + kk;
            s += s_h[e * 132 + k] * CW2[k];
        }
        s_red[q][e] = s;
    }
    __syncthreads();
    if (tid < TE && e0 + tid < EE) {
        const float cu = s_red[0][tid] + s_red[1][tid] + s_red[2][tid] + s_red[3][tid];
        const int r = s_row[tid];
        atomicAdd(&g_coord[r * 3 + 0], s_cd[tid][0] * cu);
        atomicAdd(&g_coord[r * 3 + 1], s_cd[tid][1] * cu);
        atomicAdd(&g_coord[r * 3 + 2], s_cd[tid][2] * cu);
        atomicAdd(&g_cnt[r], 1.0f);
    }
}

// ---------------- node update kernel ----------------
__global__ __launch_bounds__(128) void node_kernel(
    const float* __restrict__ h, const float* __restrict__ x,
    const float* __restrict__ NW1, const float* __restrict__ nb1,
    const float* __restrict__ NW2, const float* __restrict__ nb2,
    float* __restrict__ out_h, float* __restrict__ out_x)
{
    // aliased: phase1 s_in[n*256+k] (8192 floats); phase2 s_t[n*132+k] (4224)
    __shared__ float sbuf[8192];
    float* s_in = sbuf;
    float* s_t  = sbuf;

    const int tid = threadIdx.x;
    const int n0  = blockIdx.x * TN;

    #pragma unroll 4
    for (int n = 0; n < TN; ++n) {
        int r = n0 + n; if (r >= NN) r = NN - 1;
        s_in[n * 256 + tid]       = h[r * HH + tid];
        s_in[n * 256 + 128 + tid] = g_agg[r * HH + tid];
    }
    __syncthreads();

    float acc[TN];
    #pragma unroll
    for (int n = 0; n < TN; ++n) acc[n] = 0.0f;
    for (int k4 = 0; k4 < 64; ++k4) {
        const int k = k4 * 4;
        const float w0 = NW1[(k + 0) * HH + tid];
        const float w1 = NW1[(k + 1) * HH + tid];
        const float w2 = NW1[(k + 2) * HH + tid];
        const float w3 = NW1[(k + 3) * HH + tid];
        #pragma unroll
        for (int n = 0; n < TN; ++n) {
            const float4 v = *(const float4*)&s_in[n * 256 + k];
            acc[n] += v.x * w0;
            acc[n] += v.y * w1;
            acc[n] += v.z * w2;
            acc[n] += v.w * w3;
        }
    }
    const float bb1 = nb1[tid];
    __syncthreads();  // s_in reads done before aliased overwrite
    #pragma unroll
    for (int n = 0; n < TN; ++n) s_t[n * 132 + tid] = silu_f(acc[n] + bb1);
    __syncthreads();

    #pragma unroll
    for (int n = 0; n < TN; ++n) acc[n] = 0.0f;
    for (int k4 = 0; k4 < 32; ++k4) {
        const int k = k4 * 4;
        const float w0 = NW2[(k + 0) * HH + tid];
        const float w1 = NW2[(k + 1) * HH + tid];
        const float w2 = NW2[(k + 2) * HH + tid];
        const float w3 = NW2[(k + 3) * HH + tid];
        #pragma unroll
        for (int n = 0; n < TN; ++n) {
            const float4 v = *(const float4*)&s_t[n * 132 + k];
            acc[n] += v.x * w0;
            acc[n] += v.y * w1;
            acc[n] += v.z * w2;
            acc[n] += v.w * w3;
        }
    }
    const float bb2 = nb2[tid];
    #pragma unroll
    for (int n = 0; n < TN; ++n) {
        const int r = n0 + n;
        if (r < NN)
            out_h[r * HH + tid] = h[r * HH + tid] + acc[n] + bb2;
    }

    // x_out = x + coord_agg / max(cnt, 1)
    if (tid < TN * DD) {
        const int n = tid / 3, d = tid % 3;
        const int r = n0 + n;
        if (r < NN) {
            float cnt = g_cnt[r];
            cnt = (cnt < 1.0f) ? 1.0f : cnt;
            out_x[r * 3 + d] = x[r * 3 + d] + g_coord[r * 3 + d] / cnt;
        }
    }
}

// ---------------- launch ----------------
extern "C" void kernel_launch(void* const* d_in, const int* in_sizes, int n_in,
                              void* d_out, int out_size) {
    const float* h     = (const float*)d_in[0];
    const float* x     = (const float*)d_in[1];
    const int*   ei    = (const int*)d_in[2];
    const float* eattr = (const float*)d_in[3];
    const float* EW1   = (const float*)d_in[4];
    const float* eb1   = (const float*)d_in[5];
    const float* EW2   = (const float*)d_in[6];
    const float* eb2   = (const float*)d_in[7];
    const float* NW1   = (const float*)d_in[8];
    const float* nb1   = (const float*)d_in[9];
    const float* NW2   = (const float*)d_in[10];
    const float* nb2   = (const float*)d_in[11];
    const float* CW1   = (const float*)d_in[12];
    const float* cb1   = (const float*)d_in[13];
    const float* CW2   = (const float*)d_in[14];
    const float* AW    = (const float*)d_in[15];
    const float* ab    = (const float*)d_in[16];

    float* out_h = (float*)d_out;                       // (N, 128)
    float* out_x = (float*)d_out + (size_t)NN * HH;     // (N, 3)

    zero_kernel<<<1024, 256>>>();
    edge_kernel<<<(EE + TE - 1) / TE, 128>>>(h, x, ei, eattr,
                                             EW1, eb1, EW2, eb2,
                                             CW1, cb1, CW2, AW, ab);
    node_kernel<<<(NN + TN - 1) / TN, 128>>>(h, x, NW1, nb1, NW2, nb2,
                                             out_h, out_x);
}